// round 8
// baseline (speedup 1.0000x reference)
#include <cuda_runtime.h>

#define Nn 384
#define Dm 256
#define MARGIN 0.2f
#define ANCH 3
#define NBLK (Nn / ANCH)   // 128
#define NTHR 384
#define NWARP 12
#define JB 8

typedef unsigned long long u64;

__device__ float    g_psum[NBLK];
__device__ int      g_pcnt[NBLK];
__device__ unsigned g_flag;      // zero-init; last block resets to 0 each run

__device__ __forceinline__ u64 ffma2(u64 a, u64 b, u64 c) {
    u64 d;
    asm("fma.rn.f32x2 %0, %1, %2, %3;" : "=l"(d) : "l"(a), "l"(b), "l"(c));
    return d;
}
__device__ __forceinline__ float hadd2(u64 p) {
    float lo, hi;
    asm("mov.b64 {%0, %1}, %2;" : "=f"(lo), "=f"(hi) : "l"(p));
    return lo + hi;
}

__global__ void __launch_bounds__(NTHR, 1)
k_fused(const float* __restrict__ e, const int* __restrict__ lab,
        float* __restrict__ out) {
    __shared__ ulonglong2 ea[ANCH * 64];  // raw anchor rows (packed f32x2 pairs)
    __shared__ float  Drow[ANCH][Nn];     // raw dots -> distances (in place)
    __shared__ float  sssq[Nn];           // raw squared norms per j
    __shared__ int    slab[Nn];
    __shared__ float  pd[Nn];             // compacted positive distances
    __shared__ int    wcnt[NWARP];
    __shared__ float  rsum[NWARP];
    __shared__ int    rcnt[NWARP];
    __shared__ int    s_last;

    const int t = threadIdx.x, w = t >> 5, lane = t & 31;
    const int a0 = blockIdx.x * ANCH;

    if (t < Nn) slab[t] = lab[t];
    {
        const ulonglong2* src = (const ulonglong2*)(e + a0 * Dm);
        if (t < ANCH * 64) ea[t] = src[t];
    }
    __syncthreads();

    // ---- Phase 2: 4 lanes per j, 8 j's per warp-iteration, half-row double buffer ----
    const int jj = lane >> 2;            // which j within the group of 8 (0..7)
    const int kk = lane & 3;             // k-slice within the 4 lanes (0..3)

    ulonglong2 v0[8], v1[8];
    {
        const ulonglong2* __restrict__ row = (const ulonglong2*)(e + (w * JB + jj) * Dm);
        #pragma unroll
        for (int c = 0; c < 8; c++) v0[c] = row[kk + 4 * c];          // half 0
    }

    #pragma unroll 1
    for (int jb = w * JB; jb < Nn; jb += NWARP * JB) {               // 4 iterations
        const ulonglong2* __restrict__ row = (const ulonglong2*)(e + (jb + jj) * Dm);
        // load half 1 of current row
        #pragma unroll
        for (int c = 0; c < 8; c++) v1[c] = row[32 + kk + 4 * c];

        u64 qp = 0ull, s0 = 0ull, s1 = 0ull, s2 = 0ull;
        // compute half 0
        #pragma unroll
        for (int c = 0; c < 8; c++) {
            const int f = kk + 4 * c;
            ulonglong2 b0 = ea[0 * 64 + f];
            ulonglong2 b1 = ea[1 * 64 + f];
            ulonglong2 b2 = ea[2 * 64 + f];
            ulonglong2 vv = v0[c];
            qp = ffma2(vv.x, vv.x, qp); qp = ffma2(vv.y, vv.y, qp);
            s0 = ffma2(b0.x, vv.x, s0); s0 = ffma2(b0.y, vv.y, s0);
            s1 = ffma2(b1.x, vv.x, s1); s1 = ffma2(b1.y, vv.y, s1);
            s2 = ffma2(b2.x, vv.x, s2); s2 = ffma2(b2.y, vv.y, s2);
        }
        // prefetch next iteration's half 0 (wraps harmlessly on last iter)
        {
            const int jbn = (jb + NWARP * JB < Nn) ? (jb + NWARP * JB) : 0;
            const ulonglong2* __restrict__ rown = (const ulonglong2*)(e + (jbn + jj) * Dm);
            #pragma unroll
            for (int c = 0; c < 8; c++) v0[c] = rown[kk + 4 * c];
        }
        // compute half 1
        #pragma unroll
        for (int c = 0; c < 8; c++) {
            const int f = 32 + kk + 4 * c;
            ulonglong2 b0 = ea[0 * 64 + f];
            ulonglong2 b1 = ea[1 * 64 + f];
            ulonglong2 b2 = ea[2 * 64 + f];
            ulonglong2 vv = v1[c];
            qp = ffma2(vv.x, vv.x, qp); qp = ffma2(vv.y, vv.y, qp);
            s0 = ffma2(b0.x, vv.x, s0); s0 = ffma2(b0.y, vv.y, s0);
            s1 = ffma2(b1.x, vv.x, s1); s1 = ffma2(b1.y, vv.y, s1);
            s2 = ffma2(b2.x, vv.x, s2); s2 = ffma2(b2.y, vv.y, s2);
        }
        float q  = hadd2(qp);
        float c0 = hadd2(s0);
        float c1 = hadd2(s1);
        float c2 = hadd2(s2);
        // reduce within 4-lane groups: 2 butterfly steps, 8 j's at once
        #pragma unroll
        for (int o = 1; o < 4; o <<= 1) {
            q  += __shfl_xor_sync(0xffffffffu, q,  o);
            c0 += __shfl_xor_sync(0xffffffffu, c0, o);
            c1 += __shfl_xor_sync(0xffffffffu, c1, o);
            c2 += __shfl_xor_sync(0xffffffffu, c2, o);
        }
        if (kk == 0) {
            const int j = jb + jj;
            sssq[j]    = q;
            Drow[0][j] = c0;
            Drow[1][j] = c1;
            Drow[2][j] = c2;
        }
    }
    __syncthreads();

    // ---- Parallel epilogue: raw dot -> distance, thread t = column j ----
    {
        float sj = rsqrtf(fmaxf(sssq[t], 1e-24f));
        #pragma unroll
        for (int aa = 0; aa < ANCH; aa++) {
            float sa = rsqrtf(fmaxf(sssq[a0 + aa], 1e-24f));
            float d2 = 2.0f - 2.0f * Drow[aa][t] * sa * sj;
            d2 = fmaxf(d2, 0.0f);
            Drow[aa][t] = (d2 > 0.0f) ? sqrtf(d2) : 0.0f;
        }
    }
    __syncthreads();

    // ---- Phase 3+4: per anchor, ballot-compaction of positives + negative scan ----
    float lsum = 0.0f;
    int   lcnt = 0;
    #pragma unroll
    for (int aa = 0; aa < ANCH; aa++) {
        const int a  = a0 + aa;
        const int la = slab[a];
        bool isp = (slab[t] == la) && (t != a);
        unsigned m = __ballot_sync(0xffffffffu, isp);
        if (lane == 0) wcnt[w] = __popc(m);
        __syncthreads();
        int off = 0, npos = 0;
        #pragma unroll
        for (int i = 0; i < NWARP; i++) {
            int c = wcnt[i];
            if (i < w) off += c;
            npos += c;
        }
        if (isp) pd[off + __popc(m & ((1u << lane) - 1u))] = Drow[aa][t];
        __syncthreads();

        if (slab[t] != la) {
            float dn = Drow[aa][t];
            for (int i = 0; i < npos; i++) {
                float tm = dn - pd[i];
                // semihard & loss>0  <=>  0 < tm < MARGIN (tm==MARGIN adds 0)
                if (tm > 0.0f && tm < MARGIN) { lsum += (MARGIN - tm); lcnt++; }
            }
        }
        __syncthreads();
    }

    // ---- Block reduction (fixed order, deterministic) ----
    #pragma unroll
    for (int o = 16; o > 0; o >>= 1) {
        lsum += __shfl_xor_sync(0xffffffffu, lsum, o);
        lcnt += __shfl_xor_sync(0xffffffffu, lcnt, o);
    }
    if (lane == 0) { rsum[w] = lsum; rcnt[w] = lcnt; }
    __syncthreads();
    if (t == 0) {
        float s = 0.0f; int c = 0;
        #pragma unroll
        for (int i = 0; i < NWARP; i++) { s += rsum[i]; c += rcnt[i]; }
        g_psum[blockIdx.x] = s;
        g_pcnt[blockIdx.x] = c;
        __threadfence();
        unsigned old = atomicAdd(&g_flag, 1u);
        s_last = (old == NBLK - 1) ? 1 : 0;
    }
    __syncthreads();

    // ---- Last block folds the 128 partials (deterministic order) ----
    if (s_last) {
        float s2 = (t < NBLK) ? g_psum[t] : 0.0f;
        int   c2 = (t < NBLK) ? g_pcnt[t] : 0;
        #pragma unroll
        for (int o = 16; o > 0; o >>= 1) {
            s2 += __shfl_xor_sync(0xffffffffu, s2, o);
            c2 += __shfl_xor_sync(0xffffffffu, c2, o);
        }
        if (lane == 0 && w < 4) { rsum[w] = s2; rcnt[w] = c2; }
        __syncthreads();
        if (t == 0) {
            float ts = rsum[0] + rsum[1] + rsum[2] + rsum[3];
            int   tc = rcnt[0] + rcnt[1] + rcnt[2] + rcnt[3];
            out[0] = (tc > 0) ? (ts / (float)tc) : 0.0f;
            g_flag = 0;   // reset for next graph replay
        }
    }
}

extern "C" void kernel_launch(void* const* d_in, const int* in_sizes, int n_in,
                              void* d_out, int out_size) {
    const float* e   = (const float*)d_in[0];
    const int*   lab = (const int*)d_in[1];
    k_fused<<<NBLK, NTHR>>>(e, lab, (float*)d_out);
}

// round 9
// speedup vs baseline: 1.2034x; 1.2034x over previous
#include <cuda_runtime.h>

#define Nn 384
#define Dm 256
#define MARGIN 0.2f
#define ANCH 3
#define NBLK (Nn / ANCH)   // 128
#define NTHR 512
#define NWARP 16
#define JB 4

typedef unsigned long long u64;

__device__ float    g_psum[NBLK];
__device__ int      g_pcnt[NBLK];
__device__ unsigned g_flag;      // zero-init; last block resets to 0 each run

__device__ __forceinline__ u64 ffma2(u64 a, u64 b, u64 c) {
    u64 d;
    asm("fma.rn.f32x2 %0, %1, %2, %3;" : "=l"(d) : "l"(a), "l"(b), "l"(c));
    return d;
}
__device__ __forceinline__ float hadd2(u64 p) {
    float lo, hi;
    asm("mov.b64 {%0, %1}, %2;" : "=f"(lo), "=f"(hi) : "l"(p));
    return lo + hi;
}

__global__ void __launch_bounds__(NTHR, 1)
k_fused(const float* __restrict__ e, const int* __restrict__ lab,
        float* __restrict__ out) {
    __shared__ ulonglong2 ea[ANCH * 64];  // raw anchor rows (packed f32x2 pairs)
    __shared__ float  Drow[ANCH][Nn];     // raw dots -> distances (in place)
    __shared__ float  sssq[Nn];           // raw squared norms per j
    __shared__ int    slab[Nn];
    __shared__ float  pd[Nn];             // compacted positive distances
    __shared__ int    wcnt[NWARP];
    __shared__ float  rsum[NWARP];
    __shared__ int    rcnt[NWARP];
    __shared__ int    s_last;

    const int t = threadIdx.x, w = t >> 5, lane = t & 31;
    const int a0 = blockIdx.x * ANCH;

    if (t < Nn) slab[t] = lab[t];
    {
        const ulonglong2* src = (const ulonglong2*)(e + a0 * Dm);
        if (t < ANCH * 64) ea[t] = src[t];
    }
    __syncthreads();

    // ---- Phase 2: 8 lanes per j, 4 j's per warp, pipelined LDG, packed FMA ----
    const int jj = lane >> 3;            // which j within the group of 4
    const int kk = lane & 7;             // which k-slice (8x16B per lane)

    ulonglong2 v[8];
    {
        const ulonglong2* __restrict__ row = (const ulonglong2*)(e + (w * JB + jj) * Dm);
        #pragma unroll
        for (int c = 0; c < 8; c++) v[c] = row[kk + 8 * c];
    }

    #pragma unroll 1
    for (int jb = w * JB; jb < Nn; jb += NWARP * JB) {   // 6 iterations
        // prefetch next tile (wraps to row block 0 harmlessly on last iter)
        const int jbn = (jb + NWARP * JB < Nn) ? (jb + NWARP * JB) : 0;
        const ulonglong2* __restrict__ rown = (const ulonglong2*)(e + (jbn + jj) * Dm);
        ulonglong2 nv[8];
        #pragma unroll
        for (int c = 0; c < 8; c++) nv[c] = rown[kk + 8 * c];

        u64 qp = 0ull, s0 = 0ull, s1 = 0ull, s2 = 0ull;
        #pragma unroll
        for (int c = 0; c < 8; c++) {
            const int f = kk + 8 * c;
            ulonglong2 b0 = ea[0 * 64 + f];
            ulonglong2 b1 = ea[1 * 64 + f];
            ulonglong2 b2 = ea[2 * 64 + f];
            ulonglong2 vv = v[c];
            qp = ffma2(vv.x, vv.x, qp); qp = ffma2(vv.y, vv.y, qp);
            s0 = ffma2(b0.x, vv.x, s0); s0 = ffma2(b0.y, vv.y, s0);
            s1 = ffma2(b1.x, vv.x, s1); s1 = ffma2(b1.y, vv.y, s1);
            s2 = ffma2(b2.x, vv.x, s2); s2 = ffma2(b2.y, vv.y, s2);
        }
        float q  = hadd2(qp);
        float c0 = hadd2(s0);
        float c1 = hadd2(s1);
        float c2 = hadd2(s2);
        // reduce within 8-lane groups: 3 butterfly steps, 4 j's at once
        #pragma unroll
        for (int o = 1; o < 8; o <<= 1) {
            q  += __shfl_xor_sync(0xffffffffu, q,  o);
            c0 += __shfl_xor_sync(0xffffffffu, c0, o);
            c1 += __shfl_xor_sync(0xffffffffu, c1, o);
            c2 += __shfl_xor_sync(0xffffffffu, c2, o);
        }
        if (kk == 0) {
            const int j = jb + jj;
            sssq[j]    = q;
            Drow[0][j] = c0;
            Drow[1][j] = c1;
            Drow[2][j] = c2;
        }
        #pragma unroll
        for (int c = 0; c < 8; c++) v[c] = nv[c];
    }
    __syncthreads();

    // ---- Parallel epilogue: raw dot -> distance, thread t = column j ----
    if (t < Nn) {
        float sj = rsqrtf(fmaxf(sssq[t], 1e-24f));
        #pragma unroll
        for (int aa = 0; aa < ANCH; aa++) {
            float sa = rsqrtf(fmaxf(sssq[a0 + aa], 1e-24f));
            float d2 = 2.0f - 2.0f * Drow[aa][t] * sa * sj;
            d2 = fmaxf(d2, 0.0f);
            Drow[aa][t] = (d2 > 0.0f) ? sqrtf(d2) : 0.0f;
        }
    }
    __syncthreads();

    // ---- Phase 3+4: per anchor, ballot-compaction of positives + negative scan ----
    float lsum = 0.0f;
    int   lcnt = 0;
    #pragma unroll
    for (int aa = 0; aa < ANCH; aa++) {
        const int a  = a0 + aa;
        const int la = slab[a];
        bool isp = (t < Nn) && (slab[t] == la) && (t != a);
        unsigned m = __ballot_sync(0xffffffffu, isp);
        if (lane == 0) wcnt[w] = __popc(m);
        __syncthreads();
        int off = 0, npos = 0;
        #pragma unroll
        for (int i = 0; i < NWARP; i++) {
            int c = wcnt[i];
            if (i < w) off += c;
            npos += c;
        }
        if (isp) pd[off + __popc(m & ((1u << lane) - 1u))] = Drow[aa][t];
        __syncthreads();

        if (t < Nn && slab[t] != la) {
            float dn = Drow[aa][t];
            for (int i = 0; i < npos; i++) {
                float tm = dn - pd[i];
                // semihard & loss>0  <=>  0 < tm < MARGIN (tm==MARGIN adds 0)
                if (tm > 0.0f && tm < MARGIN) { lsum += (MARGIN - tm); lcnt++; }
            }
        }
        __syncthreads();
    }

    // ---- Block reduction (fixed order, deterministic) ----
    #pragma unroll
    for (int o = 16; o > 0; o >>= 1) {
        lsum += __shfl_xor_sync(0xffffffffu, lsum, o);
        lcnt += __shfl_xor_sync(0xffffffffu, lcnt, o);
    }
    if (lane == 0) { rsum[w] = lsum; rcnt[w] = lcnt; }
    __syncthreads();
    if (t == 0) {
        float s = 0.0f; int c = 0;
        #pragma unroll
        for (int i = 0; i < NWARP; i++) { s += rsum[i]; c += rcnt[i]; }
        g_psum[blockIdx.x] = s;
        g_pcnt[blockIdx.x] = c;
        __threadfence();
        unsigned old = atomicAdd(&g_flag, 1u);
        s_last = (old == NBLK - 1) ? 1 : 0;
    }
    __syncthreads();

    // ---- Last block folds the 128 partials (deterministic order) ----
    if (s_last) {
        float s2 = (t < NBLK) ? g_psum[t] : 0.0f;
        int   c2 = (t < NBLK) ? g_pcnt[t] : 0;
        #pragma unroll
        for (int o = 16; o > 0; o >>= 1) {
            s2 += __shfl_xor_sync(0xffffffffu, s2, o);
            c2 += __shfl_xor_sync(0xffffffffu, c2, o);
        }
        if (lane == 0 && w < 4) { rsum[w] = s2; rcnt[w] = c2; }
        __syncthreads();
        if (t == 0) {
            float ts = rsum[0] + rsum[1] + rsum[2] + rsum[3];
            int   tc = rcnt[0] + rcnt[1] + rcnt[2] + rcnt[3];
            out[0] = (tc > 0) ? (ts / (float)tc) : 0.0f;
            g_flag = 0;   // reset for next graph replay
        }
    }
}

extern "C" void kernel_launch(void* const* d_in, const int* in_sizes, int n_in,
                              void* d_out, int out_size) {
    const float* e   = (const float*)d_in[0];
    const int*   lab = (const int*)d_in[1];
    k_fused<<<NBLK, NTHR>>>(e, lab, (float*)d_out);
}

// round 10
// speedup vs baseline: 1.5000x; 1.2465x over previous
#include <cuda_runtime.h>

#define Nn 384
#define Dm 256
#define MARGIN 0.2f
#define ANCH 3
#define NBLK (Nn / ANCH)   // 128
#define NTHR 384
#define NWARP 12
#define JSTEP (NWARP * 8)  // 96 j's per round, 4 rounds

typedef unsigned long long u64;

__device__ float    g_psum[NBLK];
__device__ int      g_pcnt[NBLK];
__device__ unsigned g_flag;      // zero-init; last block resets to 0 each run

__device__ __forceinline__ u64 ffma2(u64 a, u64 b, u64 c) {
    u64 d;
    asm("fma.rn.f32x2 %0, %1, %2, %3;" : "=l"(d) : "l"(a), "l"(b), "l"(c));
    return d;
}
__device__ __forceinline__ float hadd2(u64 p) {
    float lo, hi;
    asm("mov.b64 {%0, %1}, %2;" : "=f"(lo), "=f"(hi) : "l"(p));
    return lo + hi;
}

__global__ void __launch_bounds__(NTHR, 1)
k_fused(const float* __restrict__ e, const int* __restrict__ lab,
        float* __restrict__ out) {
    __shared__ ulonglong2 ea[ANCH * 64];  // raw anchor rows (packed f32x2 pairs)
    __shared__ float  Drow[ANCH][Nn];     // raw dots -> distances (in place)
    __shared__ float  sssq[Nn];           // raw squared norms per j
    __shared__ int    slab[Nn];
    __shared__ float  pd[Nn];             // compacted positive distances
    __shared__ int    wcnt[NWARP];
    __shared__ float  rsum[NWARP];
    __shared__ int    rcnt[NWARP];
    __shared__ int    s_last;

    const int t = threadIdx.x, w = t >> 5, lane = t & 31;
    const int a0 = blockIdx.x * ANCH;

    if (t < Nn) slab[t] = lab[t];
    {
        const ulonglong2* src = (const ulonglong2*)(e + a0 * Dm);
        if (t < ANCH * 64) ea[t] = src[t];
    }
    __syncthreads();

    // ---- Phase 2: 8 lanes per j, TWO interleaved groups of 4 j's per warp ----
    const int jj = lane >> 3;            // which j within a group of 4
    const int kk = lane & 7;             // k-slice (8 x 16B per lane)

    ulonglong2 vA[8];
    {
        const ulonglong2* __restrict__ row = (const ulonglong2*)(e + (w * 8 + jj) * Dm);
        #pragma unroll
        for (int c = 0; c < 8; c++) vA[c] = row[kk + 8 * c];
    }

    #pragma unroll 1
    for (int jb = w * 8; jb < Nn; jb += JSTEP) {       // 4 iterations
        // load stream B rows (jb+4+jj)
        ulonglong2 vB[8];
        {
            const ulonglong2* __restrict__ rowB = (const ulonglong2*)(e + (jb + 4 + jj) * Dm);
            #pragma unroll
            for (int c = 0; c < 8; c++) vB[c] = rowB[kk + 8 * c];
        }

        // compute stream A
        u64 qpA = 0ull, a0p = 0ull, a1p = 0ull, a2p = 0ull;
        #pragma unroll
        for (int c = 0; c < 8; c++) {
            const int f = kk + 8 * c;
            ulonglong2 b0 = ea[0 * 64 + f];
            ulonglong2 b1 = ea[1 * 64 + f];
            ulonglong2 b2 = ea[2 * 64 + f];
            ulonglong2 vv = vA[c];
            qpA = ffma2(vv.x, vv.x, qpA); qpA = ffma2(vv.y, vv.y, qpA);
            a0p = ffma2(b0.x, vv.x, a0p); a0p = ffma2(b0.y, vv.y, a0p);
            a1p = ffma2(b1.x, vv.x, a1p); a1p = ffma2(b1.y, vv.y, a1p);
            a2p = ffma2(b2.x, vv.x, a2p); a2p = ffma2(b2.y, vv.y, a2p);
        }

        // prefetch next iteration's stream A rows (wraps harmlessly on last iter)
        {
            const int jbn = (jb + JSTEP < Nn) ? (jb + JSTEP) : 0;
            const ulonglong2* __restrict__ rown = (const ulonglong2*)(e + (jbn + jj) * Dm);
            #pragma unroll
            for (int c = 0; c < 8; c++) vA[c] = rown[kk + 8 * c];
        }

        // compute stream B
        u64 qpB = 0ull, b0p = 0ull, b1p = 0ull, b2p = 0ull;
        #pragma unroll
        for (int c = 0; c < 8; c++) {
            const int f = kk + 8 * c;
            ulonglong2 b0 = ea[0 * 64 + f];
            ulonglong2 b1 = ea[1 * 64 + f];
            ulonglong2 b2 = ea[2 * 64 + f];
            ulonglong2 vv = vB[c];
            qpB = ffma2(vv.x, vv.x, qpB); qpB = ffma2(vv.y, vv.y, qpB);
            b0p = ffma2(b0.x, vv.x, b0p); b0p = ffma2(b0.y, vv.y, b0p);
            b1p = ffma2(b1.x, vv.x, b1p); b1p = ffma2(b1.y, vv.y, b1p);
            b2p = ffma2(b2.x, vv.x, b2p); b2p = ffma2(b2.y, vv.y, b2p);
        }

        // 8 independent reduction chains, interleaved by the scheduler
        float qA  = hadd2(qpA), c0A = hadd2(a0p), c1A = hadd2(a1p), c2A = hadd2(a2p);
        float qB  = hadd2(qpB), c0B = hadd2(b0p), c1B = hadd2(b1p), c2B = hadd2(b2p);
        #pragma unroll
        for (int o = 1; o < 8; o <<= 1) {
            qA  += __shfl_xor_sync(0xffffffffu, qA,  o);
            qB  += __shfl_xor_sync(0xffffffffu, qB,  o);
            c0A += __shfl_xor_sync(0xffffffffu, c0A, o);
            c0B += __shfl_xor_sync(0xffffffffu, c0B, o);
            c1A += __shfl_xor_sync(0xffffffffu, c1A, o);
            c1B += __shfl_xor_sync(0xffffffffu, c1B, o);
            c2A += __shfl_xor_sync(0xffffffffu, c2A, o);
            c2B += __shfl_xor_sync(0xffffffffu, c2B, o);
        }
        if (kk == 0) {
            const int jA = jb + jj, jBx = jb + 4 + jj;
            sssq[jA]    = qA;   sssq[jBx]    = qB;
            Drow[0][jA] = c0A;  Drow[0][jBx] = c0B;
            Drow[1][jA] = c1A;  Drow[1][jBx] = c1B;
            Drow[2][jA] = c2A;  Drow[2][jBx] = c2B;
        }
    }
    __syncthreads();

    // ---- Parallel epilogue: raw dot -> distance, thread t = column j ----
    {
        float sj = rsqrtf(fmaxf(sssq[t], 1e-24f));
        #pragma unroll
        for (int aa = 0; aa < ANCH; aa++) {
            float sa = rsqrtf(fmaxf(sssq[a0 + aa], 1e-24f));
            float d2 = 2.0f - 2.0f * Drow[aa][t] * sa * sj;
            d2 = fmaxf(d2, 0.0f);
            Drow[aa][t] = (d2 > 0.0f) ? sqrtf(d2) : 0.0f;
        }
    }
    __syncthreads();

    // ---- Phase 3+4: per anchor, ballot-compaction of positives + negative scan ----
    float lsum = 0.0f;
    int   lcnt = 0;
    #pragma unroll
    for (int aa = 0; aa < ANCH; aa++) {
        const int a  = a0 + aa;
        const int la = slab[a];
        bool isp = (slab[t] == la) && (t != a);
        unsigned m = __ballot_sync(0xffffffffu, isp);
        if (lane == 0) wcnt[w] = __popc(m);
        __syncthreads();
        int off = 0, npos = 0;
        #pragma unroll
        for (int i = 0; i < NWARP; i++) {
            int c = wcnt[i];
            if (i < w) off += c;
            npos += c;
        }
        if (isp) pd[off + __popc(m & ((1u << lane) - 1u))] = Drow[aa][t];
        __syncthreads();

        if (slab[t] != la) {
            float dn = Drow[aa][t];
            for (int i = 0; i < npos; i++) {
                float tm = dn - pd[i];
                // semihard & loss>0  <=>  0 < tm < MARGIN (tm==MARGIN adds 0)
                if (tm > 0.0f && tm < MARGIN) { lsum += (MARGIN - tm); lcnt++; }
            }
        }
        __syncthreads();
    }

    // ---- Block reduction (fixed order, deterministic) ----
    #pragma unroll
    for (int o = 16; o > 0; o >>= 1) {
        lsum += __shfl_xor_sync(0xffffffffu, lsum, o);
        lcnt += __shfl_xor_sync(0xffffffffu, lcnt, o);
    }
    if (lane == 0) { rsum[w] = lsum; rcnt[w] = lcnt; }
    __syncthreads();
    if (t == 0) {
        float s = 0.0f; int c = 0;
        #pragma unroll
        for (int i = 0; i < NWARP; i++) { s += rsum[i]; c += rcnt[i]; }
        g_psum[blockIdx.x] = s;
        g_pcnt[blockIdx.x] = c;
        __threadfence();
        unsigned old = atomicAdd(&g_flag, 1u);
        s_last = (old == NBLK - 1) ? 1 : 0;
    }
    __syncthreads();

    // ---- Last block folds the 128 partials (deterministic order) ----
    if (s_last) {
        float s2 = (t < NBLK) ? g_psum[t] : 0.0f;
        int   c2 = (t < NBLK) ? g_pcnt[t] : 0;
        #pragma unroll
        for (int o = 16; o > 0; o >>= 1) {
            s2 += __shfl_xor_sync(0xffffffffu, s2, o);
            c2 += __shfl_xor_sync(0xffffffffu, c2, o);
        }
        if (lane == 0 && w < 4) { rsum[w] = s2; rcnt[w] = c2; }
        __syncthreads();
        if (t == 0) {
            float ts = rsum[0] + rsum[1] + rsum[2] + rsum[3];
            int   tc = rcnt[0] + rcnt[1] + rcnt[2] + rcnt[3];
            out[0] = (tc > 0) ? (ts / (float)tc) : 0.0f;
            g_flag = 0;   // reset for next graph replay
        }
    }
}

extern "C" void kernel_launch(void* const* d_in, const int* in_sizes, int n_in,
                              void* d_out, int out_size) {
    const float* e   = (const float*)d_in[0];
    const int*   lab = (const int*)d_in[1];
    k_fused<<<NBLK, NTHR>>>(e, lab, (float*)d_out);
}